// round 14
// baseline (speedup 1.0000x reference)
#include <cuda_runtime.h>
#include <cuda_fp16.h>
#include <cstdint>

// Problem constants
#define N_CB   8
#define VOCAB  1024
#define CDIM   16
#define HW     1024         // 32*32
#define DCH    128          // N_CB*CDIM
#define BHW    8192

// Output layout (float32, concatenated flat in reference order)
#define OFF_Q      0
#define OFF_IDX    1048576
#define OFF_COMMIT 1114112
#define OFF_NCB    1114113
#define OFF_NCNT   1245185
#define OFF_NW     1253377

#define DECAY_F 0.99f
#define ALPHA_F 0.01f
#define EPS_F   1e-5f

// self-cleaning accumulators (zero at load; vq_final re-zeros each replay)
__device__ float cnt_scr[N_CB * VOCAB];
__device__ float sum_scr[N_CB * VOCAB * CDIM];
__device__ float n_dev[N_CB];
__device__ float commit_scr;

static __device__ __forceinline__ uint32_t smem_u32(const void* p) {
    uint32_t a;
    asm("{ .reg .u64 t; cvta.to.shared.u64 t, %1; cvt.u32.u64 %0, t; }" : "=r"(a) : "l"(p));
    return a;
}
// split a float4 into fp16 hi and lo packed pairs
static __device__ __forceinline__ void split4(float4 f, uint32_t& hi, uint32_t& lo) {
    const __half hx = __float2half_rn(f.x), hy = __float2half_rn(f.y);
    const __half hz = __float2half_rn(f.z), hw = __float2half_rn(f.w);
    const __half lx = __float2half_rn(f.x - __half2float(hx));
    const __half ly = __float2half_rn(f.y - __half2float(hy));
    const __half lz = __float2half_rn(f.z - __half2float(hz));
    const __half lw = __float2half_rn(f.w - __half2float(hw));
    union { __half2 h2; uint32_t u; } a, b;
    a.h2 = __halves2half2(hx, hy); hi = a.u;     // low 2 dims in low half
    b.h2 = __halves2half2(lx, ly); lo = b.u;
    union { __half2 h2; uint32_t u; } c, d;
    c.h2 = __halves2half2(hz, hw);
    d.h2 = __halves2half2(lz, lw);
    // return via two calls; caller packs
    hi = a.u; lo = b.u;
    (void)c; (void)d;
}

// ---------------- smem layout (static, 46.6 KB) ----------------
#define SM_BHI 0                     // 256 rows x 48B (16 halves + 16B pad)
#define SM_BLO 12288
#define SM_AHI 24576                 // 128 rows x 48B
#define SM_ALO 30720
#define SM_ZF  36864                 // 128 x 16 fp32
#define SM_H   45056                 // 256 floats (-0.5||c||^2 chunk)
#define SM_IDX 46080                 // 128 ints
#define SM_TOT 46592

#define LDMX4(r0, r1, r2, r3, a) \
    asm volatile("ldmatrix.sync.aligned.m8n8.x4.shared.b16 {%0,%1,%2,%3}, [%4];" \
                 : "=r"(r0), "=r"(r1), "=r"(r2), "=r"(r3) : "r"(a))

// ---------- kernel 1: HMMA distance + argmin + fused epilogue ----------
// grid (64, 8): x = 128-position tile, y = codebook. 256 threads (8 warps).
// warp w owns positions tile*128 + w*16 .. +15 (MMA M-rows).
// 16 vocab per inner iteration; B fragments software-pipelined.
__global__ __launch_bounds__(256) void vq_main(const float* __restrict__ z,
                                               const float* __restrict__ cbs,
                                               const float* __restrict__ ema_count,
                                               float* out) {
    __shared__ __align__(16) char smem[SM_TOT];
    __shared__ float red[8], nred[8];
    const uint32_t sb = smem_u32(smem);
    const int cb = blockIdx.y, tile = blockIdx.x;
    const int tid = threadIdx.x, lane = tid & 31, w = tid >> 5;

    const int b      = tile >> 3;
    const int hwwarp = ((tile & 7) << 7) + w * 16;
    const float* zb  = z + (size_t)b * DCH * HW + (size_t)cb * CDIM * HW;

    // ---- build A tiles (fp16 hi/lo, 48B row stride) + fp32 z copy ----
    {
        const int r  = lane & 15;
        const int jh = lane >> 4;
        float* zf = (float*)(smem + SM_ZF);
        #pragma unroll
        for (int j2 = 0; j2 < 8; j2++) {
            const int j = j2 * 2 + jh;
            const float v = zb[j * HW + hwwarp + r];
            const __half hi = __float2half_rn(v);
            const __half lo = __float2half_rn(v - __half2float(hi));
            const int row = w * 16 + r;
            *(__half*)(smem + SM_AHI + row * 48 + j * 2) = hi;
            *(__half*)(smem + SM_ALO + row * 48 + j * 2) = lo;
            zf[row * 16 + j] = v;
        }
    }
    __syncwarp();

    // ---- A fragments (persistent) ----
    uint32_t ah0, ah1, ah2, ah3, al0, al1, al2, al3;
    {
        const uint32_t ofs = (uint32_t)(w * 16 * 48 + (lane & 15) * 48 + ((lane >> 4) << 4));
        LDMX4(ah0, ah1, ah2, ah3, sb + SM_AHI + ofs);
        LDMX4(al0, al1, al2, al3, sb + SM_ALO + ofs);
    }

    float bestA = -3.0e38f, bestB = -3.0e38f;
    int   vA = 0, vB = 0;
    const int colofs = (lane & 3) * 2;
    const int nrow   = lane >> 2;

    // B ldmatrix.x4 lane addressing (validated in r13)
    const uint32_t brow = (uint32_t)((lane & 7) + ((lane & 16) >> 1)) * 48
                        + (uint32_t)((lane & 8) << 1);

    for (int c = 0; c < 4; c++) {
        // ---- build B chunk from fp32 codebook directly (prep folded in) ----
        {
            const float4* src = (const float4*)(cbs + ((size_t)cb * VOCAB + c * 256 + tid) * CDIM);
            float4 f0 = src[0], f1 = src[1], f2 = src[2], f3 = src[3];
            uint32_t h0, h1, h2, h3, h4, h5, h6, h7;
            uint32_t l0, l1, l2, l3, l4, l5, l6, l7;
            {
                const __half a = __float2half_rn(f0.x), bq = __float2half_rn(f0.y);
                const __half cq = __float2half_rn(f0.z), dq = __float2half_rn(f0.w);
                h0 = __half2_raw(__halves2half2(a, bq)).x | ((uint32_t)__half2_raw(__halves2half2(a, bq)).y << 16);
                (void)h0;
            }
            // simpler: do it with a helper lambda
            auto sp = [](float x, float y, uint32_t& hi, uint32_t& lo) {
                const __half hx = __float2half_rn(x), hy = __float2half_rn(y);
                const __half lx = __float2half_rn(x - __half2float(hx));
                const __half ly = __float2half_rn(y - __half2float(hy));
                union { __half2 h; uint32_t u; } uh, ul;
                uh.h = __halves2half2(hx, hy);
                ul.h = __halves2half2(lx, ly);
                hi = uh.u; lo = ul.u;
            };
            sp(f0.x, f0.y, h0, l0); sp(f0.z, f0.w, h1, l1);
            sp(f1.x, f1.y, h2, l2); sp(f1.z, f1.w, h3, l3);
            sp(f2.x, f2.y, h4, l4); sp(f2.z, f2.w, h5, l5);
            sp(f3.x, f3.y, h6, l6); sp(f3.z, f3.w, h7, l7);
            *(uint4*)(smem + SM_BHI + tid * 48)      = make_uint4(h0, h1, h2, h3);
            *(uint4*)(smem + SM_BHI + tid * 48 + 16) = make_uint4(h4, h5, h6, h7);
            *(uint4*)(smem + SM_BLO + tid * 48)      = make_uint4(l0, l1, l2, l3);
            *(uint4*)(smem + SM_BLO + tid * 48 + 16) = make_uint4(l4, l5, l6, l7);
            const float s = f0.x*f0.x + f0.y*f0.y + f0.z*f0.z + f0.w*f0.w
                          + f1.x*f1.x + f1.y*f1.y + f1.z*f1.z + f1.w*f1.w
                          + f2.x*f2.x + f2.y*f2.y + f2.z*f2.z + f2.w*f2.w
                          + f3.x*f3.x + f3.y*f3.y + f3.z*f3.z + f3.w*f3.w;
            ((float*)(smem + SM_H))[tid] = -0.5f * s;
        }
        __syncthreads();

        // ---- software-pipelined MMA loop: 16 vocab / iter ----
        uint32_t cbh0, cbh1, cbh2, cbh3, cbl0, cbl1, cbl2, cbl3;
        float2 ch0, ch1;
        {
            const uint32_t a0 = sb + brow;
            LDMX4(cbh0, cbh1, cbh2, cbh3, a0 + SM_BHI);
            LDMX4(cbl0, cbl1, cbl2, cbl3, a0 + SM_BLO);
            ch0 = *(const float2*)(smem + SM_H + colofs * 4);
            ch1 = *(const float2*)(smem + SM_H + (8 + colofs) * 4);
        }

        #pragma unroll 2
        for (int it = 0; it < 16; it++) {
            uint32_t nbh0, nbh1, nbh2, nbh3, nbl0, nbl1, nbl2, nbl3;
            float2 nh0, nh1;
            if (it < 15) {                       // prefetch next iteration's B
                const uint32_t a1 = sb + (uint32_t)((it + 1) * 16 * 48) + brow;
                LDMX4(nbh0, nbh1, nbh2, nbh3, a1 + SM_BHI);
                LDMX4(nbl0, nbl1, nbl2, nbl3, a1 + SM_BLO);
                nh0 = *(const float2*)(smem + SM_H + ((it + 1) * 16 + colofs) * 4);
                nh1 = *(const float2*)(smem + SM_H + ((it + 1) * 16 + 8 + colofs) * 4);
            }

            // n-group 0: hh chain (depth 1) + cross chain (depth 2)
            float d0, d1, d2, d3, x0, x1, x2, x3;
            asm volatile("mma.sync.aligned.m16n8k16.row.col.f32.f16.f16.f32 "
                "{%0,%1,%2,%3}, {%4,%5,%6,%7}, {%8,%9}, {%10,%11,%12,%13};"
                : "=f"(d0), "=f"(d1), "=f"(d2), "=f"(d3)
                : "r"(ah0), "r"(ah1), "r"(ah2), "r"(ah3), "r"(cbh0), "r"(cbh1),
                  "f"(ch0.x), "f"(ch0.y), "f"(ch0.x), "f"(ch0.y));
            asm volatile("mma.sync.aligned.m16n8k16.row.col.f32.f16.f16.f32 "
                "{%0,%1,%2,%3}, {%4,%5,%6,%7}, {%8,%9}, {%10,%11,%12,%13};"
                : "=f"(x0), "=f"(x1), "=f"(x2), "=f"(x3)
                : "r"(ah0), "r"(ah1), "r"(ah2), "r"(ah3), "r"(cbl0), "r"(cbl1),
                  "f"(0.0f), "f"(0.0f), "f"(0.0f), "f"(0.0f));
            // n-group 1: same structure
            float e0, e1, e2, e3, y0, y1, y2, y3;
            asm volatile("mma.sync.aligned.m16n8k16.row.col.f32.f16.f16.f32 "
                "{%0,%1,%2,%3}, {%4,%5,%6,%7}, {%8,%9}, {%10,%11,%12,%13};"
                : "=f"(e0), "=f"(e1), "=f"(e2), "=f"(e3)
                : "r"(ah0), "r"(ah1), "r"(ah2), "r"(ah3), "r"(cbh2), "r"(cbh3),
                  "f"(ch1.x), "f"(ch1.y), "f"(ch1.x), "f"(ch1.y));
            asm volatile("mma.sync.aligned.m16n8k16.row.col.f32.f16.f16.f32 "
                "{%0,%1,%2,%3}, {%4,%5,%6,%7}, {%8,%9}, {%10,%11,%12,%13};"
                : "=f"(y0), "=f"(y1), "=f"(y2), "=f"(y3)
                : "r"(ah0), "r"(ah1), "r"(ah2), "r"(ah3), "r"(cbl2), "r"(cbl3),
                  "f"(0.0f), "f"(0.0f), "f"(0.0f), "f"(0.0f));
            // cross chains, second link
            asm volatile("mma.sync.aligned.m16n8k16.row.col.f32.f16.f16.f32 "
                "{%0,%1,%2,%3}, {%4,%5,%6,%7}, {%8,%9}, {%0,%1,%2,%3};"
                : "+f"(x0), "+f"(x1), "+f"(x2), "+f"(x3)
                : "r"(al0), "r"(al1), "r"(al2), "r"(al3), "r"(cbh0), "r"(cbh1));
            asm volatile("mma.sync.aligned.m16n8k16.row.col.f32.f16.f16.f32 "
                "{%0,%1,%2,%3}, {%4,%5,%6,%7}, {%8,%9}, {%0,%1,%2,%3};"
                : "+f"(y0), "+f"(y1), "+f"(y2), "+f"(y3)
                : "r"(al0), "r"(al1), "r"(al2), "r"(al3), "r"(cbh2), "r"(cbh3));

            const float s0 = d0 + x0, s1 = d1 + x1, s2 = d2 + x2, s3 = d3 + x3;
            const float t0 = e0 + y0, t1 = e1 + y1, t2 = e2 + y2, t3 = e3 + y3;

            const int v0 = c * 256 + it * 16 + colofs;
            if (s0 > bestA) { bestA = s0; vA = v0; }
            if (s1 > bestA) { bestA = s1; vA = v0 + 1; }
            if (t0 > bestA) { bestA = t0; vA = v0 + 8; }
            if (t1 > bestA) { bestA = t1; vA = v0 + 9; }
            if (s2 > bestB) { bestB = s2; vB = v0; }
            if (s3 > bestB) { bestB = s3; vB = v0 + 1; }
            if (t2 > bestB) { bestB = t2; vB = v0 + 8; }
            if (t3 > bestB) { bestB = t3; vB = v0 + 9; }

            if (it < 15) {
                cbh0 = nbh0; cbh1 = nbh1; cbh2 = nbh2; cbh3 = nbh3;
                cbl0 = nbl0; cbl1 = nbl1; cbl2 = nbl2; cbl3 = nbl3;
                ch0 = nh0; ch1 = nh1;
            }
        }
        __syncthreads();
    }

    // ---- merge argmax within each quad ----
    #pragma unroll
    for (int st = 1; st <= 2; st <<= 1) {
        float so = __shfl_xor_sync(0xFFFFFFFFu, bestA, st);
        int   vo = __shfl_xor_sync(0xFFFFFFFFu, vA, st);
        if (so > bestA || (so == bestA && vo < vA)) { bestA = so; vA = vo; }
        so = __shfl_xor_sync(0xFFFFFFFFu, bestB, st);
        vo = __shfl_xor_sync(0xFFFFFFFFu, vB, st);
        if (so > bestB || (so == bestB && vo < vB)) { bestB = so; vB = vo; }
    }
    if ((lane & 3) == 0) {
        int* idxs = (int*)(smem + SM_IDX);
        idxs[w * 16 + nrow]     = vA;
        idxs[w * 16 + nrow + 8] = vB;
    }
    __syncthreads();

    // ---- fused epilogue: 2 threads per position (8 dims each) ----
    const int pl  = tid >> 1;
    const int j0  = (tid & 1) * 8;
    const int bi  = ((int*)(smem + SM_IDX))[pl];
    const int hwp = ((tile & 7) << 7) + pl;
    const float* crow = cbs + ((size_t)cb * VOCAB + bi) * CDIM + j0;
    const float* zf   = (float*)(smem + SM_ZF) + pl * 16 + j0;
    float* qout = out + OFF_Q + (size_t)b * DCH * HW + (size_t)cb * CDIM * HW
                + (size_t)j0 * HW + hwp;
    float* wdst = sum_scr + ((size_t)cb * VOCAB + bi) * CDIM + j0;

    float locc = 0.0f;
    #pragma unroll
    for (int jj = 0; jj < 8; jj++) {
        const float zj = zf[jj];
        const float cj = crow[jj];
        qout[(size_t)jj * HW] = zj + (cj - zj);      // match zq_st rounding
        const float d = zj - cj;
        locc += d * d;
        atomicAdd(&wdst[jj], zj);
    }
    if ((tid & 1) == 0) {
        out[OFF_IDX + (size_t)b * (N_CB * HW) + (size_t)cb * HW + hwp] = (float)bi;
        atomicAdd(&cnt_scr[cb * VOCAB + bi], 1.0f);
    }

    // commitment: shuffle reduce -> 1 atomic per block
    #pragma unroll
    for (int st = 16; st > 0; st >>= 1)
        locc += __shfl_xor_sync(0xFFFFFFFFu, locc, st);
    if (lane == 0) red[w] = locc;
    __syncthreads();
    if (tid == 0) {
        float s = 0.0f;
        #pragma unroll
        for (int k = 0; k < 8; k++) s += red[k];
        atomicAdd(&commit_scr, s * (1.0f / (float)(BHW * N_CB * CDIM)));
    }

    // tile==0 blocks compute n[cb] = 0.99*sum(ema_count[cb]) + 0.01*BHW
    if (tile == 0) {
        float s = ema_count[cb * VOCAB + tid]       + ema_count[cb * VOCAB + tid + 256]
                + ema_count[cb * VOCAB + tid + 512] + ema_count[cb * VOCAB + tid + 768];
        #pragma unroll
        for (int st = 16; st > 0; st >>= 1)
            s += __shfl_xor_sync(0xFFFFFFFFu, s, st);
        if (lane == 0) nred[w] = s;
        __syncthreads();
        if (tid == 0) {
            float t = 0.0f;
            #pragma unroll
            for (int k = 0; k < 8; k++) t += nred[k];
            n_dev[cb] = DECAY_F * t + ALPHA_F * (float)BHW;
        }
    }
}

// ---------- kernel 2: EMA blend + normalized codebook + commit emit ----------
__global__ __launch_bounds__(256) void vq_final(const float* __restrict__ ema_count,
                                                const float* __restrict__ ema_weight,
                                                float* out) {
    const int i  = blockIdx.x * 256 + threadIdx.x;    // 0 .. 131071
    const int cb = i >> 14;
    const int v  = (i >> 4) & (VOCAB - 1);
    const int j  = i & 15;

    if (i == 0) { out[OFF_COMMIT] = commit_scr; commit_scr = 0.0f; }

    const float sums = sum_scr[i];
    sum_scr[i] = 0.0f;                                // self-clean
    const float nw = DECAY_F * ema_weight[i] + ALPHA_F * sums;
    out[OFF_NW + i] = nw;

    const float craw = cnt_scr[cb * VOCAB + v];
    __syncwarp();
    if (j == 0) cnt_scr[cb * VOCAB + v] = 0.0f;       // self-clean

    const float ncnt = DECAY_F * ema_count[cb * VOCAB + v] + ALPHA_F * craw;
    if (j == 0) out[OFF_NCNT + cb * VOCAB + v] = ncnt;

    const float n = n_dev[cb];
    const float countv = (ncnt + EPS_F) / (n + VOCAB * EPS_F) * n;
    out[OFF_NCB + i] = __fdividef(nw, countv);
}

extern "C" void kernel_launch(void* const* d_in, const int* in_sizes, int n_in,
                              void* d_out, int out_size) {
    const float* z   = (const float*)d_in[0];
    const float* cbs = (const float*)d_in[1];
    const float* ec  = (const float*)d_in[2];
    const float* ew  = (const float*)d_in[3];
    float* out = (float*)d_out;

    dim3 gmain(64, N_CB);
    vq_main<<<gmain, 256>>>(z, cbs, ec, out);
    vq_final<<<512, 256>>>(ec, ew, out);
}

// round 15
// speedup vs baseline: 1.2138x; 1.2138x over previous
#include <cuda_runtime.h>
#include <cuda_fp16.h>
#include <cstdint>

// Problem constants
#define N_CB   8
#define VOCAB  1024
#define CDIM   16
#define HW     1024         // 32*32
#define DCH    128          // N_CB*CDIM
#define BHW    8192

// Output layout (float32, concatenated flat in reference order)
#define OFF_Q      0
#define OFF_IDX    1048576
#define OFF_COMMIT 1114112
#define OFF_NCB    1114113
#define OFF_NCNT   1245185
#define OFF_NW     1253377

#define DECAY_F 0.99f
#define ALPHA_F 0.01f
#define EPS_F   1e-5f

// self-cleaning accumulators (zero at load; vq_final re-zeros each replay)
__device__ float cnt_scr[N_CB * VOCAB];
__device__ float sum_scr[N_CB * VOCAB * CDIM];
__device__ float n_dev[N_CB];
__device__ float commit_scr;

static __device__ __forceinline__ uint32_t smem_u32(const void* p) {
    uint32_t a;
    asm("{ .reg .u64 t; cvta.to.shared.u64 t, %1; cvt.u32.u64 %0, t; }" : "=r"(a) : "l"(p));
    return a;
}
// split two floats into packed fp16 hi pair and lo pair
static __device__ __forceinline__ void sp2(float x, float y, uint32_t& hi, uint32_t& lo) {
    const __half hx = __float2half_rn(x), hy = __float2half_rn(y);
    const __half lx = __float2half_rn(x - __half2float(hx));
    const __half ly = __float2half_rn(y - __half2float(hy));
    union { __half2 h; uint32_t u; } uh, ul;
    uh.h = __halves2half2(hx, hy);
    ul.h = __halves2half2(lx, ly);
    hi = uh.u; lo = ul.u;
}

// ---------------- smem layout (static, 46.6 KB) ----------------
#define SM_BHI 0                     // 256 rows x 48B (16 halves + 16B pad)
#define SM_BLO 12288
#define SM_AHI 24576                 // 128 rows x 48B
#define SM_ALO 30720
#define SM_ZF  36864                 // 128 x 16 fp32
#define SM_H   45056                 // 256 floats (-0.5||c||^2 chunk)
#define SM_IDX 46080                 // 128 ints
#define SM_TOT 46592

// ---------- kernel 1: HMMA distance + argmin + fused epilogue ----------
// grid (64, 8): x = 128-position tile, y = codebook. 256 threads (8 warps).
// warp w owns positions tile*128 + w*16 .. +15 (MMA M-rows).
// Inner loop: 16 vocab per iteration (two n8 groups via ldmatrix.x4). (r13 structure)
__global__ __launch_bounds__(256) void vq_main(const float* __restrict__ z,
                                               const float* __restrict__ cbs,
                                               const float* __restrict__ ema_count,
                                               float* out) {
    __shared__ __align__(16) char smem[SM_TOT];
    __shared__ float red[8], nred[8];
    const uint32_t sb = smem_u32(smem);
    const int cb = blockIdx.y, tile = blockIdx.x;
    const int tid = threadIdx.x, lane = tid & 31, w = tid >> 5;

    const int b      = tile >> 3;
    const int hwwarp = ((tile & 7) << 7) + w * 16;
    const float* zb  = z + (size_t)b * DCH * HW + (size_t)cb * CDIM * HW;

    // ---- build A tiles (fp16 hi/lo, 48B row stride) + fp32 z copy ----
    {
        const int r  = lane & 15;          // row within warp tile
        const int jh = lane >> 4;          // 0/1 selects dim parity group
        float* zf = (float*)(smem + SM_ZF);
        #pragma unroll
        for (int j2 = 0; j2 < 8; j2++) {
            const int j = j2 * 2 + jh;
            const float v = zb[j * HW + hwwarp + r];
            const __half hi = __float2half_rn(v);
            const __half lo = __float2half_rn(v - __half2float(hi));
            const int row = w * 16 + r;
            *(__half*)(smem + SM_AHI + row * 48 + j * 2) = hi;
            *(__half*)(smem + SM_ALO + row * 48 + j * 2) = lo;
            zf[row * 16 + j] = v;
        }
    }
    __syncwarp();

    // ---- A fragments (persistent): ldmatrix.x4, canonical m16n16 pattern ----
    uint32_t ah0, ah1, ah2, ah3, al0, al1, al2, al3;
    {
        const uint32_t ofs = (uint32_t)(w * 16 * 48 + (lane & 15) * 48 + ((lane >> 4) << 4));
        uint32_t a = sb + SM_AHI + ofs;
        asm volatile("ldmatrix.sync.aligned.m8n8.x4.shared.b16 {%0,%1,%2,%3}, [%4];"
                     : "=r"(ah0), "=r"(ah1), "=r"(ah2), "=r"(ah3) : "r"(a));
        a = sb + SM_ALO + ofs;
        asm volatile("ldmatrix.sync.aligned.m8n8.x4.shared.b16 {%0,%1,%2,%3}, [%4];"
                     : "=r"(al0), "=r"(al1), "=r"(al2), "=r"(al3) : "r"(a));
    }

    float bestA = -3.0e38f, bestB = -3.0e38f;
    int   vA = 0, vB = 0;
    const int colofs = (lane & 3) * 2;     // D/B column (vocab) offset within n8
    const int nrow   = lane >> 2;          // D row group

    // B ldmatrix.x4 lane addressing (validated in r13)
    const uint32_t brow = (uint32_t)((lane & 7) + ((lane & 16) >> 1)) * 48
                        + (uint32_t)((lane & 8) << 1);

    for (int c = 0; c < 4; c++) {
        // ---- build B chunk from fp32 codebook directly (prep folded in) ----
        {
            const float4* src = (const float4*)(cbs + ((size_t)cb * VOCAB + c * 256 + tid) * CDIM);
            float4 f0 = src[0], f1 = src[1], f2 = src[2], f3 = src[3];
            uint32_t h0, h1, h2, h3, h4, h5, h6, h7;
            uint32_t l0, l1, l2, l3, l4, l5, l6, l7;
            sp2(f0.x, f0.y, h0, l0); sp2(f0.z, f0.w, h1, l1);
            sp2(f1.x, f1.y, h2, l2); sp2(f1.z, f1.w, h3, l3);
            sp2(f2.x, f2.y, h4, l4); sp2(f2.z, f2.w, h5, l5);
            sp2(f3.x, f3.y, h6, l6); sp2(f3.z, f3.w, h7, l7);
            *(uint4*)(smem + SM_BHI + tid * 48)      = make_uint4(h0, h1, h2, h3);
            *(uint4*)(smem + SM_BHI + tid * 48 + 16) = make_uint4(h4, h5, h6, h7);
            *(uint4*)(smem + SM_BLO + tid * 48)      = make_uint4(l0, l1, l2, l3);
            *(uint4*)(smem + SM_BLO + tid * 48 + 16) = make_uint4(l4, l5, l6, l7);
            const float s = f0.x*f0.x + f0.y*f0.y + f0.z*f0.z + f0.w*f0.w
                          + f1.x*f1.x + f1.y*f1.y + f1.z*f1.z + f1.w*f1.w
                          + f2.x*f2.x + f2.y*f2.y + f2.z*f2.z + f2.w*f2.w
                          + f3.x*f3.x + f3.y*f3.y + f3.z*f3.z + f3.w*f3.w;
            ((float*)(smem + SM_H))[tid] = -0.5f * s;
        }
        __syncthreads();

        #pragma unroll 2
        for (int it = 0; it < 16; it++) {
            const int vl = it * 16;
            const uint32_t baddr = sb + (uint32_t)(vl * 48) + brow;
            uint32_t bh0, bh1, bh2, bh3, bl0, bl1, bl2, bl3;
            asm volatile("ldmatrix.sync.aligned.m8n8.x4.shared.b16 {%0,%1,%2,%3}, [%4];"
                         : "=r"(bh0), "=r"(bh1), "=r"(bh2), "=r"(bh3) : "r"(baddr + SM_BHI));
            asm volatile("ldmatrix.sync.aligned.m8n8.x4.shared.b16 {%0,%1,%2,%3}, [%4];"
                         : "=r"(bl0), "=r"(bl1), "=r"(bl2), "=r"(bl3) : "r"(baddr + SM_BLO));
            const float2 h0 = *(const float2*)(smem + SM_H + (vl + colofs) * 4);
            const float2 h1 = *(const float2*)(smem + SM_H + (vl + 8 + colofs) * 4);

            float d0, d1, d2, d3, e0, e1, e2, e3;
            // n-group 0 (vocab vl..vl+7)
            asm volatile("mma.sync.aligned.m16n8k16.row.col.f32.f16.f16.f32 "
                "{%0,%1,%2,%3}, {%4,%5,%6,%7}, {%8,%9}, {%10,%11,%12,%13};"
                : "=f"(d0), "=f"(d1), "=f"(d2), "=f"(d3)
                : "r"(ah0), "r"(ah1), "r"(ah2), "r"(ah3), "r"(bh0), "r"(bh1),
                  "f"(h0.x), "f"(h0.y), "f"(h0.x), "f"(h0.y));
            // n-group 1 (vocab vl+8..vl+15)
            asm volatile("mma.sync.aligned.m16n8k16.row.col.f32.f16.f16.f32 "
                "{%0,%1,%2,%3}, {%4,%5,%6,%7}, {%8,%9}, {%10,%11,%12,%13};"
                : "=f"(e0), "=f"(e1), "=f"(e2), "=f"(e3)
                : "r"(ah0), "r"(ah1), "r"(ah2), "r"(ah3), "r"(bh2), "r"(bh3),
                  "f"(h1.x), "f"(h1.y), "f"(h1.x), "f"(h1.y));
            asm volatile("mma.sync.aligned.m16n8k16.row.col.f32.f16.f16.f32 "
                "{%0,%1,%2,%3}, {%4,%5,%6,%7}, {%8,%9}, {%0,%1,%2,%3};"
                : "+f"(d0), "+f"(d1), "+f"(d2), "+f"(d3)
                : "r"(al0), "r"(al1), "r"(al2), "r"(al3), "r"(bh0), "r"(bh1));
            asm volatile("mma.sync.aligned.m16n8k16.row.col.f32.f16.f16.f32 "
                "{%0,%1,%2,%3}, {%4,%5,%6,%7}, {%8,%9}, {%0,%1,%2,%3};"
                : "+f"(e0), "+f"(e1), "+f"(e2), "+f"(e3)
                : "r"(al0), "r"(al1), "r"(al2), "r"(al3), "r"(bh2), "r"(bh3));
            asm volatile("mma.sync.aligned.m16n8k16.row.col.f32.f16.f16.f32 "
                "{%0,%1,%2,%3}, {%4,%5,%6,%7}, {%8,%9}, {%0,%1,%2,%3};"
                : "+f"(d0), "+f"(d1), "+f"(d2), "+f"(d3)
                : "r"(ah0), "r"(ah1), "r"(ah2), "r"(ah3), "r"(bl0), "r"(bl1));
            asm volatile("mma.sync.aligned.m16n8k16.row.col.f32.f16.f16.f32 "
                "{%0,%1,%2,%3}, {%4,%5,%6,%7}, {%8,%9}, {%0,%1,%2,%3};"
                : "+f"(e0), "+f"(e1), "+f"(e2), "+f"(e3)
                : "r"(ah0), "r"(ah1), "r"(ah2), "r"(ah3), "r"(bl2), "r"(bl3));

            const int v0 = c * 256 + vl + colofs;
            if (d0 > bestA) { bestA = d0; vA = v0; }
            if (d1 > bestA) { bestA = d1; vA = v0 + 1; }
            if (e0 > bestA) { bestA = e0; vA = v0 + 8; }
            if (e1 > bestA) { bestA = e1; vA = v0 + 9; }
            if (d2 > bestB) { bestB = d2; vB = v0; }
            if (d3 > bestB) { bestB = d3; vB = v0 + 1; }
            if (e2 > bestB) { bestB = e2; vB = v0 + 8; }
            if (e3 > bestB) { bestB = e3; vB = v0 + 9; }
        }
        __syncthreads();
    }

    // ---- merge argmax within each quad (lanes sharing a D row) ----
    #pragma unroll
    for (int st = 1; st <= 2; st <<= 1) {
        float so = __shfl_xor_sync(0xFFFFFFFFu, bestA, st);
        int   vo = __shfl_xor_sync(0xFFFFFFFFu, vA, st);
        if (so > bestA || (so == bestA && vo < vA)) { bestA = so; vA = vo; }
        so = __shfl_xor_sync(0xFFFFFFFFu, bestB, st);
        vo = __shfl_xor_sync(0xFFFFFFFFu, vB, st);
        if (so > bestB || (so == bestB && vo < vB)) { bestB = so; vB = vo; }
    }
    if ((lane & 3) == 0) {
        int* idxs = (int*)(smem + SM_IDX);
        idxs[w * 16 + nrow]     = vA;
        idxs[w * 16 + nrow + 8] = vB;
    }
    __syncthreads();

    // ---- fused epilogue: 2 threads per position (8 dims each) ----
    const int pl  = tid >> 1;
    const int j0  = (tid & 1) * 8;
    const int bi  = ((int*)(smem + SM_IDX))[pl];
    const int hwp = ((tile & 7) << 7) + pl;
    const float* crow = cbs + ((size_t)cb * VOCAB + bi) * CDIM + j0;
    const float* zf   = (float*)(smem + SM_ZF) + pl * 16 + j0;
    float* qout = out + OFF_Q + (size_t)b * DCH * HW + (size_t)cb * CDIM * HW
                + (size_t)j0 * HW + hwp;
    float* wdst = sum_scr + ((size_t)cb * VOCAB + bi) * CDIM + j0;

    float locc = 0.0f;
    #pragma unroll
    for (int jj = 0; jj < 8; jj++) {
        const float zj = zf[jj];
        const float cj = crow[jj];
        qout[(size_t)jj * HW] = zj + (cj - zj);      // match zq_st rounding
        const float d = zj - cj;
        locc += d * d;
        atomicAdd(&wdst[jj], zj);
    }
    if ((tid & 1) == 0) {
        out[OFF_IDX + (size_t)b * (N_CB * HW) + (size_t)cb * HW + hwp] = (float)bi;
        atomicAdd(&cnt_scr[cb * VOCAB + bi], 1.0f);
    }

    // commitment: shuffle reduce -> 1 atomic per block
    #pragma unroll
    for (int st = 16; st > 0; st >>= 1)
        locc += __shfl_xor_sync(0xFFFFFFFFu, locc, st);
    if (lane == 0) red[w] = locc;
    __syncthreads();
    if (tid == 0) {
        float s = 0.0f;
        #pragma unroll
        for (int k = 0; k < 8; k++) s += red[k];
        atomicAdd(&commit_scr, s * (1.0f / (float)(BHW * N_CB * CDIM)));
    }

    // tile==0 blocks compute n[cb] = 0.99*sum(ema_count[cb]) + 0.01*BHW
    if (tile == 0) {
        float s = ema_count[cb * VOCAB + tid]       + ema_count[cb * VOCAB + tid + 256]
                + ema_count[cb * VOCAB + tid + 512] + ema_count[cb * VOCAB + tid + 768];
        #pragma unroll
        for (int st = 16; st > 0; st >>= 1)
            s += __shfl_xor_sync(0xFFFFFFFFu, s, st);
        if (lane == 0) nred[w] = s;
        __syncthreads();
        if (tid == 0) {
            float t = 0.0f;
            #pragma unroll
            for (int k = 0; k < 8; k++) t += nred[k];
            n_dev[cb] = DECAY_F * t + ALPHA_F * (float)BHW;
        }
    }
}

// ---------- kernel 2: EMA blend + normalized codebook + commit emit ----------
__global__ __launch_bounds__(256) void vq_final(const float* __restrict__ ema_count,
                                                const float* __restrict__ ema_weight,
                                                float* out) {
    const int i  = blockIdx.x * 256 + threadIdx.x;    // 0 .. 131071
    const int cb = i >> 14;
    const int v  = (i >> 4) & (VOCAB - 1);
    const int j  = i & 15;

    if (i == 0) { out[OFF_COMMIT] = commit_scr; commit_scr = 0.0f; }

    const float sums = sum_scr[i];
    sum_scr[i] = 0.0f;                                // self-clean
    const float nw = DECAY_F * ema_weight[i] + ALPHA_F * sums;
    out[OFF_NW + i] = nw;

    const float craw = cnt_scr[cb * VOCAB + v];
    __syncwarp();
    if (j == 0) cnt_scr[cb * VOCAB + v] = 0.0f;       // self-clean

    const float ncnt = DECAY_F * ema_count[cb * VOCAB + v] + ALPHA_F * craw;
    if (j == 0) out[OFF_NCNT + cb * VOCAB + v] = ncnt;

    const float n = n_dev[cb];
    const float countv = (ncnt + EPS_F) / (n + VOCAB * EPS_F) * n;
    out[OFF_NCB + i] = __fdividef(nw, countv);
}

extern "C" void kernel_launch(void* const* d_in, const int* in_sizes, int n_in,
                              void* d_out, int out_size) {
    const float* z   = (const float*)d_in[0];
    const float* cbs = (const float*)d_in[1];
    const float* ec  = (const float*)d_in[2];
    const float* ew  = (const float*)d_in[3];
    float* out = (float*)d_out;

    dim3 gmain(64, N_CB);
    vq_main<<<gmain, 256>>>(z, cbs, ec, out);
    vq_final<<<512, 256>>>(ec, ew, out);
}